// round 8
// baseline (speedup 1.0000x reference)
#include <cuda_runtime.h>
#include <cuda_bf16.h>
#include <math.h>

// Problem constants (T=256, B=256, I=H=512)
#define TT 256
#define BB 256
#define KK 512          // u32 words per split row (hi/lo pair words)
#define HH 512
#define G3 1536
#define LN_EPS 1e-5f
#define NBLK 96         // persistent grid: 4 m-tiles x 24 n-tiles of 64x64
#define WPITCH 520      // W smem row pitch (words): conflict-free LDS.64

// Scratch (static device globals — allocation-free)
__device__ float    g_gi[(size_t)TT * BB * G3];  // (T*B, 3H) input projections
__device__ float    g_gh[(size_t)BB * G3];       // (B, 3H) per-step hidden proj
__device__ float    g_h [(size_t)BB * HH];       // (B, H) fp32 hidden state
__device__ unsigned g_xs [(size_t)TT * BB * KK]; // x split (bf16 hi/lo words)
__device__ unsigned g_wis[(size_t)G3 * KK];      // W_ih split
__device__ unsigned g_whs[(size_t)G3 * KK];      // W_hh split
__device__ unsigned g_hs [(size_t)BB * KK];      // h split (updated each step)

// Grid-wide barrier state (generation counter, replay-safe)
__device__ volatile unsigned g_gen;
__device__ unsigned g_cnt;

__device__ __forceinline__ void gbar(unsigned& gen) {
    __syncthreads();
    if (threadIdx.x == 0) {
        __threadfence();
        unsigned t = atomicAdd(&g_cnt, 1u);
        if (t == NBLK - 1u) {
            g_cnt = 0u;
            __threadfence();
            atomicExch((unsigned*)&g_gen, gen + 1u);   // release
        } else {
            while (g_gen < gen + 1u) { __nanosleep(64); }
            __threadfence();                           // acquire
        }
        gen = gen + 1u;
    }
    __syncthreads();
}

// ---------------------------------------------------------------------------
// bf16 split helpers. word(2i)=hi bf16x2 of elems(2i,2i+1), word(2i+1)=lo.
// ---------------------------------------------------------------------------
__device__ __forceinline__ uint2 split2(float x, float y) {
    __nv_bfloat16 hx = __float2bfloat16(x);
    __nv_bfloat16 hy = __float2bfloat16(y);
    __nv_bfloat16 lx = __float2bfloat16(x - __bfloat162float(hx));
    __nv_bfloat16 ly = __float2bfloat16(y - __bfloat162float(hy));
    __nv_bfloat162 hp; hp.x = hx; hp.y = hy;
    __nv_bfloat162 lp; lp.x = lx; lp.y = ly;
    uint2 o;
    o.x = *reinterpret_cast<unsigned*>(&hp);
    o.y = *reinterpret_cast<unsigned*>(&lp);
    return o;
}

__global__ void split_pairs(const float* __restrict__ src,
                            unsigned* __restrict__ dst, int npairs) {
    int i = blockIdx.x * 256 + threadIdx.x;
    if (i >= npairs) return;
    float2 v = ((const float2*)src)[i];
    ((uint2*)dst)[i] = split2(v.x, v.y);
}

__device__ __forceinline__ void mma_bf16(float* d, unsigned a0, unsigned a1,
                                         unsigned a2, unsigned a3,
                                         unsigned b0, unsigned b1) {
    asm volatile(
        "mma.sync.aligned.m16n8k16.row.col.f32.bf16.bf16.f32 "
        "{%0,%1,%2,%3},{%4,%5,%6,%7},{%8,%9},{%0,%1,%2,%3};"
        : "+f"(d[0]), "+f"(d[1]), "+f"(d[2]), "+f"(d[3])
        : "r"(a0), "r"(a1), "r"(a2), "r"(a3), "r"(b0), "r"(b1));
}

// ---------------------------------------------------------------------------
// gi GEMM (phase 1, fully parallel): proven R6 kernel, 64x64 tile.
// ---------------------------------------------------------------------------
__global__ __launch_bounds__(256) void gemm_bf16s(
    const unsigned* __restrict__ A, const unsigned* __restrict__ W,
    const float* __restrict__ bias, float* __restrict__ C, int ldc)
{
    __shared__ unsigned sA[2][64 * 24];
    __shared__ unsigned sW[2][64 * 24];

    const int tid  = threadIdx.x;
    const int wid  = tid >> 5;
    const int lane = tid & 31;
    const int qr   = lane >> 2;
    const int qc   = lane & 3;
    const int m0   = blockIdx.y * 64;
    const int n0   = blockIdx.x * 64;
    const int m_off = (wid >> 2) * 32;
    const int n_off = (wid & 3) * 16;

    const int srow = tid >> 2;
    const int sq   = tid & 3;
    const int ws0  = 2 * ((2 * sq) & 3) + ((2 * sq) >> 2);
    const int ws1  = 2 * ((2 * sq + 1) & 3) + ((2 * sq + 1) >> 2);
    const unsigned* Wp = W + (size_t)(n0 + srow) * KK + sq * 4;
    const unsigned* Ap = A + (size_t)(m0 + srow) * KK + sq * 4;

    float acc[2][2][4];
    #pragma unroll
    for (int mt = 0; mt < 2; mt++)
        #pragma unroll
        for (int nt = 0; nt < 2; nt++)
            #pragma unroll
            for (int c = 0; c < 4; c++) acc[mt][nt][c] = 0.0f;

    {
        uint4 wv = *(const uint4*)Wp;
        uint4 av = *(const uint4*)Ap;
        sW[0][srow * 24 + ws0]     = wv.x;
        sW[0][srow * 24 + 8 + ws0] = wv.y;
        sW[0][srow * 24 + ws1]     = wv.z;
        sW[0][srow * 24 + 8 + ws1] = wv.w;
        sA[0][srow * 24 + ws0]     = av.x;
        sA[0][srow * 24 + 8 + ws0] = av.y;
        sA[0][srow * 24 + ws1]     = av.z;
        sA[0][srow * 24 + 8 + ws1] = av.w;
    }
    __syncthreads();

    uint4 wnx, anx;
    for (int ch = 0; ch < 32; ++ch) {
        const int cur = ch & 1;
        if (ch < 31) {
            wnx = *(const uint4*)(Wp + (ch + 1) * 16);
            anx = *(const uint4*)(Ap + (ch + 1) * 16);
        }

        const unsigned* pA = sA[cur];
        const unsigned* pW = sW[cur];
        unsigned ah[2][4], al[2][4];
        #pragma unroll
        for (int mt = 0; mt < 2; mt++) {
            const int r = m_off + mt * 16 + qr;
            uint2 h0 = *(const uint2*)(pA + r * 24 + 2 * qc);
            uint2 h1 = *(const uint2*)(pA + (r + 8) * 24 + 2 * qc);
            uint2 l0 = *(const uint2*)(pA + r * 24 + 8 + 2 * qc);
            uint2 l1 = *(const uint2*)(pA + (r + 8) * 24 + 8 + 2 * qc);
            ah[mt][0] = h0.x; ah[mt][1] = h1.x; ah[mt][2] = h0.y; ah[mt][3] = h1.y;
            al[mt][0] = l0.x; al[mt][1] = l1.x; al[mt][2] = l0.y; al[mt][3] = l1.y;
        }
        #pragma unroll
        for (int nt = 0; nt < 2; nt++) {
            const int rn = n_off + nt * 8 + qr;
            uint2 bh = *(const uint2*)(pW + rn * 24 + 2 * qc);
            uint2 bl = *(const uint2*)(pW + rn * 24 + 8 + 2 * qc);
            #pragma unroll
            for (int mt = 0; mt < 2; mt++) {
                mma_bf16(acc[mt][nt], ah[mt][0], ah[mt][1], ah[mt][2], ah[mt][3], bh.x, bh.y);
                mma_bf16(acc[mt][nt], ah[mt][0], ah[mt][1], ah[mt][2], ah[mt][3], bl.x, bl.y);
                mma_bf16(acc[mt][nt], al[mt][0], al[mt][1], al[mt][2], al[mt][3], bh.x, bh.y);
            }
        }

        if (ch < 31) {
            const int nb = cur ^ 1;
            sW[nb][srow * 24 + ws0]     = wnx.x;
            sW[nb][srow * 24 + 8 + ws0] = wnx.y;
            sW[nb][srow * 24 + ws1]     = wnx.z;
            sW[nb][srow * 24 + 8 + ws1] = wnx.w;
            sA[nb][srow * 24 + ws0]     = anx.x;
            sA[nb][srow * 24 + 8 + ws0] = anx.y;
            sA[nb][srow * 24 + ws1]     = anx.z;
            sA[nb][srow * 24 + 8 + ws1] = anx.w;
        }
        __syncthreads();
    }

    #pragma unroll
    for (int mt = 0; mt < 2; mt++)
        #pragma unroll
        for (int nt = 0; nt < 2; nt++) {
            const int r = m0 + m_off + mt * 16 + qr;
            const int c = n0 + n_off + nt * 8 + qc * 2;
            const float bx = bias[c], by = bias[c + 1];
            *(float2*)(C + (size_t)r * ldc + c) =
                make_float2(acc[mt][nt][0] + bx, acc[mt][nt][1] + by);
            *(float2*)(C + (size_t)(r + 8) * ldc + c) =
                make_float2(acc[mt][nt][2] + bx, acc[mt][nt][3] + by);
        }
}

// ---------------------------------------------------------------------------
// Persistent recurrence: one launch for all 256 steps.
// Per block: W_hh split slice (64 rows x 512 words) resident in SMEM in the
// permuted conflict-free layout. Per step: [GEMM -> gbar -> gate+LN -> gbar].
// ---------------------------------------------------------------------------
__global__ __launch_bounds__(256, 1) void gru_persist(
    const float* __restrict__ masks, const float* __restrict__ b_hh,
    const float* __restrict__ ln_w,  const float* __restrict__ ln_b,
    float* __restrict__ y)
{
    extern __shared__ unsigned smem[];
    unsigned* sW = smem;                 // [64][WPITCH]
    unsigned* sA = smem + 64 * WPITCH;   // [2][64*24]

    const int tid  = threadIdx.x;
    const int wid  = tid >> 5;
    const int lane = tid & 31;
    const int qr   = lane >> 2;
    const int qc   = lane & 3;
    const int bx   = blockIdx.x;
    const int m0   = (bx / 24) * 64;
    const int n0   = (bx % 24) * 64;
    const int m_off = (wid >> 2) * 32;
    const int n_off = (wid & 3) * 16;

    // One-time: stage W_hh split slice into permuted SMEM layout.
    // slot(j) = 2*(j&3)+(j>>2); hi at +slot, lo at +8+slot within chunk.
    for (int idx = tid; idx < 64 * 256; idx += 256) {
        const int r  = idx >> 8;
        const int p  = idx & 255;          // pair index within row
        const int ch = p >> 3;
        const int j  = p & 7;
        const int s  = 2 * (j & 3) + (j >> 2);
        uint2 v = *(const uint2*)(g_whs + (size_t)(n0 + r) * KK + 2 * p);
        sW[r * WPITCH + ch * 16 + s]     = v.x;
        sW[r * WPITCH + ch * 16 + 8 + s] = v.y;
    }

    // A staging map (per chunk): 4 threads/row, one uint4 = pairs 2q,2q+1
    const int arow = tid >> 2;
    const int aq   = tid & 3;
    const int as0  = 2 * ((2 * aq) & 3) + ((2 * aq) >> 2);
    const int as1  = 2 * ((2 * aq + 1) & 3) + ((2 * aq + 1) >> 2);
    const unsigned* Ap = g_hs + (size_t)(m0 + arow) * KK + aq * 4;

    // hoisted epilogue bias
    float2 bq[2];
    #pragma unroll
    for (int nt = 0; nt < 2; nt++)
        bq[nt] = *(const float2*)(b_hh + n0 + n_off + nt * 8 + qc * 2);

    const int brow = bx + NBLK * wid;     // phase-B row (1 warp per row)
    unsigned gen = g_gen;                 // replay-safe generation base
    __syncthreads();

    for (int t = 0; t < TT; ++t) {
        // ---------- Phase A: gh tile = (h*mask) @ W_hh^T + b_hh ----------
        const unsigned mz =
            (__ldg(masks + t * BB + m0 + arow) != 0.0f) ? 0xFFFFFFFFu : 0u;

        float acc[2][2][4];
        #pragma unroll
        for (int mt = 0; mt < 2; mt++)
            #pragma unroll
            for (int nt = 0; nt < 2; nt++)
                #pragma unroll
                for (int c = 0; c < 4; c++) acc[mt][nt][c] = 0.0f;

        {
            uint4 av = __ldcg((const uint4*)Ap);
            sA[arow * 24 + as0]     = av.x & mz;
            sA[arow * 24 + 8 + as0] = av.y & mz;
            sA[arow * 24 + as1]     = av.z & mz;
            sA[arow * 24 + 8 + as1] = av.w & mz;
        }
        __syncthreads();

        uint4 anx;
        for (int ch = 0; ch < 32; ++ch) {
            const int cur = ch & 1;
            if (ch < 31) anx = __ldcg((const uint4*)(Ap + (ch + 1) * 16));

            const unsigned* pA = sA + cur * (64 * 24);
            unsigned ah[2][4], al[2][4];
            #pragma unroll
            for (int mt = 0; mt < 2; mt++) {
                const int r = m_off + mt * 16 + qr;
                uint2 h0 = *(const uint2*)(pA + r * 24 + 2 * qc);
                uint2 h1 = *(const uint2*)(pA + (r + 8) * 24 + 2 * qc);
                uint2 l0 = *(const uint2*)(pA + r * 24 + 8 + 2 * qc);
                uint2 l1 = *(const uint2*)(pA + (r + 8) * 24 + 8 + 2 * qc);
                ah[mt][0] = h0.x; ah[mt][1] = h1.x; ah[mt][2] = h0.y; ah[mt][3] = h1.y;
                al[mt][0] = l0.x; al[mt][1] = l1.x; al[mt][2] = l0.y; al[mt][3] = l1.y;
            }
            #pragma unroll
            for (int nt = 0; nt < 2; nt++) {
                const int rn = n_off + nt * 8 + qr;
                const unsigned* wb = sW + rn * WPITCH + ch * 16;
                uint2 bh = *(const uint2*)(wb + 2 * qc);
                uint2 bl = *(const uint2*)(wb + 8 + 2 * qc);
                #pragma unroll
                for (int mt = 0; mt < 2; mt++) {
                    mma_bf16(acc[mt][nt], ah[mt][0], ah[mt][1], ah[mt][2], ah[mt][3], bh.x, bh.y);
                    mma_bf16(acc[mt][nt], ah[mt][0], ah[mt][1], ah[mt][2], ah[mt][3], bl.x, bl.y);
                    mma_bf16(acc[mt][nt], al[mt][0], al[mt][1], al[mt][2], al[mt][3], bh.x, bh.y);
                }
            }

            if (ch < 31) {
                unsigned* d = sA + (cur ^ 1) * (64 * 24) + arow * 24;
                d[as0]     = anx.x & mz;
                d[8 + as0] = anx.y & mz;
                d[as1]     = anx.z & mz;
                d[8 + as1] = anx.w & mz;
            }
            __syncthreads();
        }

        #pragma unroll
        for (int mt = 0; mt < 2; mt++)
            #pragma unroll
            for (int nt = 0; nt < 2; nt++) {
                const int r = m0 + m_off + mt * 16 + qr;
                const int c = n0 + n_off + nt * 8 + qc * 2;
                *(float2*)(g_gh + (size_t)r * G3 + c) =
                    make_float2(acc[mt][nt][0] + bq[nt].x, acc[mt][nt][1] + bq[nt].y);
                *(float2*)(g_gh + (size_t)(r + 8) * G3 + c) =
                    make_float2(acc[mt][nt][2] + bq[nt].x, acc[mt][nt][3] + bq[nt].y);
            }
        gbar(gen);   // gh globally visible

        // ---------- Phase B: gates + h update + LayerNorm ----------
        if (brow < BB) {
            const float m = __ldg(masks + t * BB + brow);
            const float* gi = g_gi + ((size_t)t * BB + brow) * G3;
            const float* gh = g_gh + (size_t)brow * G3;
            float* hp = g_h + (size_t)brow * HH;
            float hv[16];
            float s1 = 0.f, s2 = 0.f;
            #pragma unroll
            for (int i = 0; i < 8; i++) {
                const int j = i * 64 + 2 * lane;
                float2 gir = *(const float2*)(gi + j);
                float2 giz = *(const float2*)(gi + HH + j);
                float2 gin = *(const float2*)(gi + 2 * HH + j);
                float2 ghr = __ldcg((const float2*)(gh + j));
                float2 ghz = __ldcg((const float2*)(gh + HH + j));
                float2 ghn = __ldcg((const float2*)(gh + 2 * HH + j));
                float2 hvp = *(const float2*)(hp + j);
                const float r0 = 1.f / (1.f + expf(-(gir.x + ghr.x)));
                const float r1 = 1.f / (1.f + expf(-(gir.y + ghr.y)));
                const float z0 = 1.f / (1.f + expf(-(giz.x + ghz.x)));
                const float z1 = 1.f / (1.f + expf(-(giz.y + ghz.y)));
                const float nn0 = tanhf(gin.x + r0 * ghn.x);
                const float nn1 = tanhf(gin.y + r1 * ghn.y);
                const float h0 = (1.f - z0) * nn0 + z0 * (hvp.x * m);
                const float h1 = (1.f - z1) * nn1 + z1 * (hvp.y * m);
                hv[2 * i] = h0; hv[2 * i + 1] = h1;
                s1 += h0 + h1; s2 += h0 * h0 + h1 * h1;
            }
            #pragma unroll
            for (int o = 16; o > 0; o >>= 1) {
                s1 += __shfl_xor_sync(0xFFFFFFFFu, s1, o);
                s2 += __shfl_xor_sync(0xFFFFFFFFu, s2, o);
            }
            const float mu   = s1 * (1.f / HH);
            const float rstd = rsqrtf(s2 * (1.f / HH) - mu * mu + LN_EPS);
            float* yp = y + ((size_t)t * BB + brow) * HH;
            uint2* hsp = (uint2*)(g_hs + (size_t)brow * KK);
            #pragma unroll
            for (int i = 0; i < 8; i++) {
                const int j = i * 64 + 2 * lane;
                const float h0 = hv[2 * i], h1 = hv[2 * i + 1];
                *(float2*)(hp + j) = make_float2(h0, h1);
                hsp[j >> 1] = split2(h0, h1);
                float2 w  = *(const float2*)(ln_w + j);
                float2 bb = *(const float2*)(ln_b + j);
                *(float2*)(yp + j) = make_float2((h0 - mu) * rstd * w.x + bb.x,
                                                 (h1 - mu) * rstd * w.y + bb.y);
            }
        }
        gbar(gen);   // h split visible before next step's GEMM
    }
}

// ---------------------------------------------------------------------------
extern "C" void kernel_launch(void* const* d_in, const int* in_sizes, int n_in,
                              void* d_out, int out_size)
{
    const float* x     = (const float*)d_in[0];
    const float* h0    = (const float*)d_in[1];
    const float* masks = (const float*)d_in[2];
    const float* W_ih  = (const float*)d_in[3];
    const float* W_hh  = (const float*)d_in[4];
    const float* b_ih  = (const float*)d_in[5];
    const float* b_hh  = (const float*)d_in[6];
    const float* ln_w  = (const float*)d_in[7];
    const float* ln_b  = (const float*)d_in[8];

    float* y  = (float*)d_out;
    float* hT = y + (size_t)TT * BB * HH;

    float *gi_p, *h_p;
    unsigned *xs_p, *wis_p, *whs_p, *hs_p;
    cudaGetSymbolAddress((void**)&gi_p,  g_gi);
    cudaGetSymbolAddress((void**)&h_p,   g_h);
    cudaGetSymbolAddress((void**)&xs_p,  g_xs);
    cudaGetSymbolAddress((void**)&wis_p, g_wis);
    cudaGetSymbolAddress((void**)&whs_p, g_whs);
    cudaGetSymbolAddress((void**)&hs_p,  g_hs);

    const int smem_bytes = (64 * WPITCH + 2 * 64 * 24) * (int)sizeof(unsigned);
    cudaFuncSetAttribute(gru_persist,
                         cudaFuncAttributeMaxDynamicSharedMemorySize, smem_bytes);

    // Phase 0: one-time bf16 hi/lo splits
    const int npx = TT * BB * KK / 2;
    const int npw = G3 * KK / 2;
    const int nph = BB * HH / 2;
    split_pairs<<<(npx + 255) / 256, 256>>>(x,    xs_p,  npx);
    split_pairs<<<(npw + 255) / 256, 256>>>(W_ih, wis_p, npw);
    split_pairs<<<(npw + 255) / 256, 256>>>(W_hh, whs_p, npw);
    split_pairs<<<(nph + 255) / 256, 256>>>(h0,   hs_p,  nph);
    cudaMemcpyAsync(h_p, h0, (size_t)BB * HH * sizeof(float),
                    cudaMemcpyDeviceToDevice);

    // Phase 1: gi = x @ W_ih^T + b_ih (fully parallel)
    gemm_bf16s<<<dim3(G3 / 64, (TT * BB) / 64), 256>>>(xs_p, wis_p, b_ih, gi_p, G3);

    // Phase 2: entire recurrence in ONE persistent launch (96 blocks = 1 wave)
    gru_persist<<<NBLK, 256, smem_bytes>>>(masks, b_hh, ln_w, ln_b, y);

    // hT output
    cudaMemcpyAsync(hT, h_p, (size_t)BB * HH * sizeof(float),
                    cudaMemcpyDeviceToDevice);
}